// round 11
// baseline (speedup 1.0000x reference)
#include <cuda_runtime.h>
#include <cuda_bf16.h>
#include <cstdint>

// x[B=2048, C=16, S=2000] fp32.
// Attention branch is identity (softmax rows sum to 1), so:
//   out[b,j,s] = LN_j( sum_c Wp[j,c]*x[b,c,s] + bp[j] ) * gp[j] + hp[j]
//
// R11: cp.async.bulk (TMA-path) producer ring decouples HBM reads from
// register-limited warp prefetch. 3-stage smem ring of 32 KB units
// (16 ch x 500 s), single-thread producer, 125 compute lanes per CTA,
// packed FFMA2 math (R8), STG.cs direct stores.

#define CN      16
#define SN      2000
#define BN      2048
#define LN_EPS  1e-5f
#define RING    3
#define SEG     500                    // s positions per unit
#define SEG_B   (SEG * 4)              // 2000 bytes per channel row
#define STAGE_B (CN * SEG_B)           // 32000 bytes per stage
#define NUNITS  (BN * 4)               // 8192 units (b, quarter)
#define GRIDN   296
#define BLOCK   128
#define ACTIVE  125                    // 125 * 4 s = 500 s

typedef unsigned long long u64;

__device__ __forceinline__ u64 fma2(u64 a, u64 b, u64 c) {
    u64 d; asm("fma.rn.f32x2 %0, %1, %2, %3;" : "=l"(d) : "l"(a), "l"(b), "l"(c)); return d;
}
__device__ __forceinline__ u64 add2(u64 a, u64 b) {
    u64 d; asm("add.rn.f32x2 %0, %1, %2;" : "=l"(d) : "l"(a), "l"(b)); return d;
}
__device__ __forceinline__ u64 mul2(u64 a, u64 b) {
    u64 d; asm("mul.rn.f32x2 %0, %1, %2;" : "=l"(d) : "l"(a), "l"(b)); return d;
}
__device__ __forceinline__ u64 pack2(float lo, float hi) {
    u64 d; asm("mov.b64 %0, {%1, %2};" : "=l"(d) : "f"(lo), "f"(hi)); return d;
}
__device__ __forceinline__ void unpack2(u64 a, float& lo, float& hi) {
    asm("mov.b64 {%0, %1}, %2;" : "=f"(lo), "=f"(hi) : "l"(a));
}
__device__ __forceinline__ void stcs128(float* p, u64 lo, u64 hi) {
    asm volatile("st.global.cs.v2.b64 [%0], {%1, %2};" :: "l"(p), "l"(lo), "l"(hi) : "memory");
}

__device__ __forceinline__ void mbar_init(uint32_t bar, uint32_t cnt) {
    asm volatile("mbarrier.init.shared.b64 [%0], %1;" :: "r"(bar), "r"(cnt) : "memory");
}
__device__ __forceinline__ void mbar_arrive(uint32_t bar) {
    asm volatile("mbarrier.arrive.shared.b64 _, [%0];" :: "r"(bar) : "memory");
}
__device__ __forceinline__ void mbar_expect_tx(uint32_t bar, uint32_t bytes) {
    asm volatile("mbarrier.arrive.expect_tx.shared.b64 _, [%0], %1;" :: "r"(bar), "r"(bytes) : "memory");
}
__device__ __forceinline__ void mbar_wait_acq(uint32_t bar, uint32_t par) {
    uint32_t done;
    asm volatile(
        "{\n\t.reg .pred p;\n\t"
        "mbarrier.try_wait.parity.acquire.cta.shared::cta.b64 p, [%1], %2;\n\t"
        "selp.b32 %0, 1, 0, p;\n\t}"
        : "=r"(done) : "r"(bar), "r"(par) : "memory");
    if (!done) {
        asm volatile(
            "{\n\t.reg .pred P1;\n\t"
            "WL%=:\n\t"
            "mbarrier.try_wait.parity.acquire.cta.shared::cta.b64 P1, [%0], %1, 0x989680;\n\t"
            "@P1 bra.uni WD%=;\n\t"
            "bra.uni WL%=;\n\t"
            "WD%=:\n\t}"
            :: "r"(bar), "r"(par) : "memory");
    }
}
__device__ __forceinline__ void mbar_wait_rlx(uint32_t bar, uint32_t par) {
    uint32_t done;
    asm volatile(
        "{\n\t.reg .pred p;\n\t"
        "mbarrier.try_wait.parity.relaxed.cta.shared::cta.b64 p, [%1], %2, 0x989680;\n\t"
        "selp.b32 %0, 1, 0, p;\n\t}"
        : "=r"(done) : "r"(bar), "r"(par) : "memory");
    if (!done) {
        asm volatile(
            "{\n\t.reg .pred P1;\n\t"
            "WL%=:\n\t"
            "mbarrier.try_wait.parity.relaxed.cta.shared::cta.b64 P1, [%0], %1, 0x989680;\n\t"
            "@P1 bra.uni WD%=;\n\t"
            "bra.uni WL%=;\n\t"
            "WD%=:\n\t}"
            :: "r"(bar), "r"(par) : "memory");
    }
}
__device__ __forceinline__ void bulk_g2s(uint32_t dst, const void* src, uint32_t bytes, uint32_t bar) {
    asm volatile(
        "cp.async.bulk.shared::cta.global.mbarrier::complete_tx::bytes [%0], [%1], %2, [%3];"
        :: "r"(dst), "l"(src), "r"(bytes), "r"(bar) : "memory");
}
__device__ __forceinline__ uint32_t s2u32(const void* p) {
    uint32_t a;
    asm("{ .reg .u64 t; cvta.to.shared.u64 t, %1; cvt.u32.u64 %0, t; }" : "=r"(a) : "l"(p));
    return a;
}

// Dynamic smem layout: [0,48): 3x(full,empty) mbarrier pairs; [128, 128+3*32000): stages.
extern __shared__ __align__(128) unsigned char dsm[];

__global__ __launch_bounds__(BLOCK) void fused_proj_ln_r11(
    const float* __restrict__ x,
    const float* __restrict__ Wp,
    const float* __restrict__ bp,
    const float* __restrict__ gp,
    const float* __restrict__ hp,
    float* __restrict__ out)
{
    __shared__ u64 sW2[CN * CN];
    __shared__ u64 sb2[CN], sg2[CN], sh2[CN];

    const int t = threadIdx.x;
    for (int i = t; i < CN * CN; i += BLOCK) { const float w = Wp[i]; sW2[i] = pack2(w, w); }
    if (t < CN) {
        sb2[t] = pack2(bp[t], bp[t]);
        sg2[t] = pack2(gp[t], gp[t]);
        sh2[t] = pack2(hp[t], hp[t]);
    }

    const uint32_t sbase = s2u32(dsm);
    if (t == 0) {
#pragma unroll
        for (int s = 0; s < RING; ++s) {
            mbar_init(sbase + s * 16u, 1u);          // full: producer expect_tx arrive
            mbar_init(sbase + s * 16u + 8u, BLOCK);  // empty: all threads arrive
        }
    }
    __syncthreads();

    // Prologue: fill all RING slots (NUNITS >> 3*gridDim, always valid).
    if (t == 0) {
#pragma unroll
        for (int k = 0; k < RING; ++k) {
            const unsigned u = blockIdx.x + (unsigned)k * GRIDN;
            const unsigned b = u >> 2, q = u & 3u;
            const float* src = x + (size_t)b * (CN * SN) + q * SEG;
            const uint32_t bar = sbase + (uint32_t)k * 16u;
            const uint32_t dst = sbase + 128u + (uint32_t)k * STAGE_B;
            mbar_expect_tx(bar, STAGE_B);
#pragma unroll
            for (int c = 0; c < CN; ++c)
                bulk_g2s(dst + c * SEG_B, src + (size_t)c * SN, SEG_B, bar);
        }
    }

    unsigned k = 0;
    for (unsigned u = blockIdx.x; u < NUNITS; u += GRIDN, ++k) {
        const unsigned slot = k % RING;
        const unsigned par  = (k / RING) & 1u;
        const uint32_t fbar = sbase + slot * 16u;
        const uint32_t ebar = fbar + 8u;

        mbar_wait_acq(fbar, par);

        if (t < ACTIVE) {
            const unsigned b = u >> 2, q = u & 3u;
            const unsigned char* stage = dsm + 128 + slot * STAGE_B;

            // Stage reads: conflict-free LDS.128 (contiguous 16B/lane).
            ulonglong2 v[CN];
#pragma unroll
            for (int c = 0; c < CN; ++c)
                v[c] = *reinterpret_cast<const ulonglong2*>(stage + c * SEG_B + t * 16);

            u64 ylo[CN], yhi[CN];
#pragma unroll
            for (int j = 0; j < CN; ++j) {
                u64 alo = sb2[j], ahi = sb2[j];
#pragma unroll
                for (int c = 0; c < CN; ++c) {
                    const u64 w = sW2[j * CN + c];
                    alo = fma2(w, v[c].x, alo);
                    ahi = fma2(w, v[c].y, ahi);
                }
                ylo[j] = alo; yhi[j] = ahi;
            }

            u64 slo = ylo[0], shi = yhi[0];
#pragma unroll
            for (int j = 1; j < CN; ++j) { slo = add2(slo, ylo[j]); shi = add2(shi, yhi[j]); }
            const u64 ninv2  = pack2(-1.0f / (float)CN, -1.0f / (float)CN);
            const u64 negmul = mul2(slo, ninv2);
            const u64 negmuh = mul2(shi, ninv2);

            u64 vlo = 0ull, vhi = 0ull;
#pragma unroll
            for (int j = 0; j < CN; ++j) {
                const u64 dlo = add2(ylo[j], negmul);
                const u64 dhi = add2(yhi[j], negmuh);
                vlo = fma2(dlo, dlo, vlo);
                vhi = fma2(dhi, dhi, vhi);
            }
            float va, vb2, vc2, vd;
            unpack2(vlo, va, vb2);
            unpack2(vhi, vc2, vd);
            const float inv = 1.0f / (float)CN;
            const u64 rslo = pack2(rsqrtf(va  * inv + LN_EPS), rsqrtf(vb2 * inv + LN_EPS));
            const u64 rshi = pack2(rsqrtf(vc2 * inv + LN_EPS), rsqrtf(vd  * inv + LN_EPS));

            float* ob = out + (size_t)b * (CN * SN) + q * SEG + t * 4;
#pragma unroll
            for (int j = 0; j < CN; ++j) {
                const u64 g2 = sg2[j];
                const u64 h2 = sh2[j];
                const u64 dlo = add2(ylo[j], negmul);
                const u64 dhi = add2(yhi[j], negmuh);
                stcs128(ob + (size_t)j * SN,
                        fma2(mul2(dlo, rslo), g2, h2),
                        fma2(mul2(dhi, rshi), g2, h2));
            }
        }

        mbar_arrive(ebar);   // all BLOCK threads (release)

        if (t == 0) {
            const unsigned un = u + RING * GRIDN;
            if (un < NUNITS) {
                mbar_wait_rlx(ebar, par);   // slot free (this round's 128 arrivals)
                const unsigned b = un >> 2, q = un & 3u;
                const float* src = x + (size_t)b * (CN * SN) + q * SEG;
                mbar_expect_tx(fbar, STAGE_B);
                const uint32_t dst = sbase + 128u + slot * STAGE_B;
#pragma unroll
                for (int c = 0; c < CN; ++c)
                    bulk_g2s(dst + c * SEG_B, src + (size_t)c * SN, SEG_B, fbar);
            }
        }
    }
}

extern "C" void kernel_launch(void* const* d_in, const int* in_sizes, int n_in,
                              void* d_out, int out_size)
{
    // metadata order: x, Wq, bq, gq, hq, Wk, bk, gk, hk, Wp, bp, gp, hp
    const float* x  = (const float*)d_in[0];
    const float* Wp = (const float*)d_in[9];
    const float* bp = (const float*)d_in[10];
    const float* gp = (const float*)d_in[11];
    const float* hp = (const float*)d_in[12];
    float* out = (float*)d_out;

    const int dynsmem = 128 + RING * STAGE_B;   // 96,128 bytes
    cudaFuncSetAttribute(fused_proj_ln_r11,
                         cudaFuncAttributeMaxDynamicSharedMemorySize, dynsmem);
    fused_proj_ln_r11<<<GRIDN, BLOCK, dynsmem>>>(x, Wp, bp, gp, hp, out);
}

// round 13
// speedup vs baseline: 2.0750x; 2.0750x over previous
#include <cuda_runtime.h>
#include <cuda_bf16.h>
#include <cstdint>

// x[B=2048, C=16, S=2000] fp32.
// Attention branch is identity (softmax rows sum to 1), so:
//   out[b,j,s] = LN_j( sum_c Wp[j,c]*x[b,c,s] + bp[j] ) * gp[j] + hp[j]
//
// R12: R8 skeleton (persistent 296x256, packed FFMA2, STG.cs) but loads are
// cp.async.cg into thread-private smem slots, 3-stage ring at 8-channel
// (half-tile) granularity, prefetched 3 phases ahead. Loads stay in flight
// during compute => continuous DRAM demand (R8's 11%-duty burstiness was the
// 70%-of-peak limiter).

#define CN      16
#define SN      2000
#define BN      2048
#define LN_EPS  1e-5f
#define GRIDN   296
#define BLOCK   256
#define GPB     500                       // 4-s units per b
#define TUNITS  ((unsigned)BN * GPB)      // 1,024,000 thread-units
#define RING    3
#define CH_B    (BLOCK * 16)              // 4096 B per channel row per stage
#define PH_B    (8 * CH_B)                // 32768 B per stage (8 channels)

typedef unsigned long long u64;

__device__ __forceinline__ u64 fma2(u64 a, u64 b, u64 c) {
    u64 d; asm("fma.rn.f32x2 %0, %1, %2, %3;" : "=l"(d) : "l"(a), "l"(b), "l"(c)); return d;
}
__device__ __forceinline__ u64 add2(u64 a, u64 b) {
    u64 d; asm("add.rn.f32x2 %0, %1, %2;" : "=l"(d) : "l"(a), "l"(b)); return d;
}
__device__ __forceinline__ u64 mul2(u64 a, u64 b) {
    u64 d; asm("mul.rn.f32x2 %0, %1, %2;" : "=l"(d) : "l"(a), "l"(b)); return d;
}
__device__ __forceinline__ u64 pack2(float lo, float hi) {
    u64 d; asm("mov.b64 %0, {%1, %2};" : "=l"(d) : "f"(lo), "f"(hi)); return d;
}
__device__ __forceinline__ void unpack2(u64 a, float& lo, float& hi) {
    asm("mov.b64 {%0, %1}, %2;" : "=f"(lo), "=f"(hi) : "l"(a));
}
__device__ __forceinline__ void stcs128(float* p, u64 lo, u64 hi) {
    asm volatile("st.global.cs.v2.b64 [%0], {%1, %2};" :: "l"(p), "l"(lo), "l"(hi) : "memory");
}
__device__ __forceinline__ uint32_t s2u32(const void* p) {
    uint32_t a;
    asm("{ .reg .u64 t; cvta.to.shared.u64 t, %1; cvt.u32.u64 %0, t; }" : "=r"(a) : "l"(p));
    return a;
}
__device__ __forceinline__ void cpasync16(uint32_t dst, const float* src) {
    asm volatile("cp.async.cg.shared.global [%0], [%1], 16;" :: "r"(dst), "l"(src) : "memory");
}
#define CP_COMMIT() asm volatile("cp.async.commit_group;" ::: "memory")
#define CP_WAIT2()  asm volatile("cp.async.wait_group 2;" ::: "memory")

extern __shared__ __align__(128) unsigned char dsm[];   // RING * PH_B bytes

// Prefetch half-tile (8 channels) of thread-unit u, half h, into ring slot.
__device__ __forceinline__ void prefetch_half(
    const float* __restrict__ x, unsigned u, int h, uint32_t slot_base_t)
{
    if (u < TUNITS) {
        const unsigned b  = u / GPB;
        const unsigned s4 = (u - b * GPB) * 4u;
        const float* src = x + (size_t)b * (CN * SN) + (size_t)(h * 8) * SN + s4;
#pragma unroll
        for (int c8 = 0; c8 < 8; ++c8)
            cpasync16(slot_base_t + (uint32_t)c8 * CH_B, src + (size_t)c8 * SN);
    }
    CP_COMMIT();   // commit even when empty to keep group accounting uniform
}

__global__ __launch_bounds__(BLOCK, 2) void fused_proj_ln_r12(
    const float* __restrict__ x,
    const float* __restrict__ Wp,
    const float* __restrict__ bp,
    const float* __restrict__ gp,
    const float* __restrict__ hp,
    float* __restrict__ out)
{
    __shared__ u64 sW2[CN * CN];
    __shared__ u64 sb2[CN], sg2[CN], sh2[CN];

    const int t = threadIdx.x;
    if (t < CN * CN) { const float w = Wp[t]; sW2[t] = pack2(w, w); }
    if (t < CN) {
        sb2[t] = pack2(bp[t], bp[t]);
        sg2[t] = pack2(gp[t], gp[t]);
        sh2[t] = pack2(hp[t], hp[t]);
    }

    const uint32_t sbt = s2u32(dsm) + (uint32_t)t * 16u;   // this thread's column
    const unsigned g0     = blockIdx.x * (unsigned)BLOCK + (unsigned)t;
    const unsigned stride = GRIDN * (unsigned)BLOCK;        // 75,776

    // Prologue: phases 0,1,2 -> slots 0,1,2  (round0 A, round0 B, round1 A)
    prefetch_half(x, g0,          0, sbt + 0u * PH_B);
    prefetch_half(x, g0,          1, sbt + 1u * PH_B);
    prefetch_half(x, g0 + stride, 0, sbt + 2u * PH_B);

    __syncthreads();   // weights ready (prefetches are thread-private)

    unsigned slot = 0;   // ring cursor: read slot == refill slot, advance per phase
    for (unsigned u = g0; u < TUNITS; u += stride) {
        const unsigned b  = u / GPB;
        const unsigned s4 = (u - b * GPB) * 4u;

        u64 ylo[CN], yhi[CN];
        ulonglong2 v[8];

        // ---------- phase A: channels 0..7 ----------
        CP_WAIT2();
        {
            const uint32_t sb_ = sbt + slot * (uint32_t)PH_B;
#pragma unroll
            for (int c8 = 0; c8 < 8; ++c8) {
                asm volatile("ld.shared.v2.b64 {%0, %1}, [%2];"
                             : "=l"(v[c8].x), "=l"(v[c8].y)
                             : "r"(sb_ + (uint32_t)c8 * CH_B));
            }
        }
        // refill this slot with phase q+3 (round k+1, half B) — write lands
        // >=400cyc later (DRAM), LDS above completes in ~30cyc: safe.
        prefetch_half(x, u + stride, 1, sbt + slot * (uint32_t)PH_B);
        slot = (slot + 1u) % RING;

#pragma unroll
        for (int j = 0; j < CN; ++j) {
            u64 alo = sb2[j], ahi = sb2[j];
#pragma unroll
            for (int c8 = 0; c8 < 8; ++c8) {
                const u64 w = sW2[j * CN + c8];
                alo = fma2(w, v[c8].x, alo);
                ahi = fma2(w, v[c8].y, ahi);
            }
            ylo[j] = alo; yhi[j] = ahi;
        }

        // ---------- phase B: channels 8..15 ----------
        CP_WAIT2();
        {
            const uint32_t sb_ = sbt + slot * (uint32_t)PH_B;
#pragma unroll
            for (int c8 = 0; c8 < 8; ++c8) {
                asm volatile("ld.shared.v2.b64 {%0, %1}, [%2];"
                             : "=l"(v[c8].x), "=l"(v[c8].y)
                             : "r"(sb_ + (uint32_t)c8 * CH_B));
            }
        }
        prefetch_half(x, u + 2u * stride, 0, sbt + slot * (uint32_t)PH_B);
        slot = (slot + 1u) % RING;

#pragma unroll
        for (int j = 0; j < CN; ++j) {
            u64 alo = ylo[j], ahi = yhi[j];
#pragma unroll
            for (int c8 = 0; c8 < 8; ++c8) {
                const u64 w = sW2[j * CN + 8 + c8];
                alo = fma2(w, v[c8].x, alo);
                ahi = fma2(w, v[c8].y, ahi);
            }
            ylo[j] = alo; yhi[j] = ahi;
        }

        // ---------- LayerNorm + store ----------
        u64 slo = ylo[0], shi = yhi[0];
#pragma unroll
        for (int j = 1; j < CN; ++j) { slo = add2(slo, ylo[j]); shi = add2(shi, yhi[j]); }
        const u64 ninv2  = pack2(-1.0f / (float)CN, -1.0f / (float)CN);
        const u64 negmul = mul2(slo, ninv2);
        const u64 negmuh = mul2(shi, ninv2);

        u64 vlo = 0ull, vhi = 0ull;
#pragma unroll
        for (int j = 0; j < CN; ++j) {
            const u64 dlo = add2(ylo[j], negmul);
            const u64 dhi = add2(yhi[j], negmuh);
            vlo = fma2(dlo, dlo, vlo);
            vhi = fma2(dhi, dhi, vhi);
        }
        float va, vb2, vc2, vd;
        unpack2(vlo, va, vb2);
        unpack2(vhi, vc2, vd);
        const float inv = 1.0f / (float)CN;
        const u64 rslo = pack2(rsqrtf(va  * inv + LN_EPS), rsqrtf(vb2 * inv + LN_EPS));
        const u64 rshi = pack2(rsqrtf(vc2 * inv + LN_EPS), rsqrtf(vd  * inv + LN_EPS));

        float* ob = out + (size_t)b * (CN * SN) + s4;
#pragma unroll
        for (int j = 0; j < CN; ++j) {
            const u64 g2 = sg2[j];
            const u64 h2 = sh2[j];
            const u64 dlo = add2(ylo[j], negmul);
            const u64 dhi = add2(yhi[j], negmuh);
            stcs128(ob + (size_t)j * SN,
                    fma2(mul2(dlo, rslo), g2, h2),
                    fma2(mul2(dhi, rshi), g2, h2));
        }
    }
}

extern "C" void kernel_launch(void* const* d_in, const int* in_sizes, int n_in,
                              void* d_out, int out_size)
{
    // metadata order: x, Wq, bq, gq, hq, Wk, bk, gk, hk, Wp, bp, gp, hp
    const float* x  = (const float*)d_in[0];
    const float* Wp = (const float*)d_in[9];
    const float* bp = (const float*)d_in[10];
    const float* gp = (const float*)d_in[11];
    const float* hp = (const float*)d_in[12];
    float* out = (float*)d_out;

    const int dynsmem = RING * PH_B;   // 98,304 B per CTA (2 CTAs/SM = 192 KB)
    cudaFuncSetAttribute(fused_proj_ln_r12,
                         cudaFuncAttributeMaxDynamicSharedMemorySize, dynsmem);
    fused_proj_ln_r12<<<GRIDN, BLOCK, dynsmem>>>(x, Wp, bp, gp, hp, out);
}

// round 15
// speedup vs baseline: 2.3001x; 1.1085x over previous
#include <cuda_runtime.h>
#include <cuda_bf16.h>
#include <cstdint>

// x[B=2048, C=16, S=2000] fp32.
// Attention branch is identity (softmax rows sum to 1), so:
//   out[b,j,s] = LN_j( sum_c Wp[j,c]*x[b,c,s] + bp[j] ) * gp[j] + hp[j]
//
// R14: R8 skeleton + software-pipelined register double-buffering.
// Loads issued in 4-channel quarters, two register buffers, load(Q+1)
// issued BEFORE fma(Q); next tile's Q0 issued before the Q3-FMA/LN/store
// epilogue. Keeps a load group in flight ~continuously (R8's 38% duty
// -> ~100%), which the calibrated model says is the 70%-DRAM limiter.

#define CN      16
#define SN      2000
#define BN      2048
#define LN_EPS  1e-5f
#define GRIDN   296
#define BLOCK   256
#define GPB     500                       // 4-s units per b
#define TUNITS  ((unsigned)BN * GPB)      // 1,024,000 thread-units

typedef unsigned long long u64;

__device__ __forceinline__ u64 fma2(u64 a, u64 b, u64 c) {
    u64 d; asm("fma.rn.f32x2 %0, %1, %2, %3;" : "=l"(d) : "l"(a), "l"(b), "l"(c)); return d;
}
__device__ __forceinline__ u64 add2(u64 a, u64 b) {
    u64 d; asm("add.rn.f32x2 %0, %1, %2;" : "=l"(d) : "l"(a), "l"(b)); return d;
}
__device__ __forceinline__ u64 mul2(u64 a, u64 b) {
    u64 d; asm("mul.rn.f32x2 %0, %1, %2;" : "=l"(d) : "l"(a), "l"(b)); return d;
}
__device__ __forceinline__ u64 pack2(float lo, float hi) {
    u64 d; asm("mov.b64 %0, {%1, %2};" : "=l"(d) : "f"(lo), "f"(hi)); return d;
}
__device__ __forceinline__ void unpack2(u64 a, float& lo, float& hi) {
    asm("mov.b64 {%0, %1}, %2;" : "=f"(lo), "=f"(hi) : "l"(a));
}
__device__ __forceinline__ void stcs128(float* p, u64 lo, u64 hi) {
    asm volatile("st.global.cs.v2.b64 [%0], {%1, %2};" :: "l"(p), "l"(lo), "l"(hi) : "memory");
}

// Load a 4-channel quarter (4x LDG.128, coalesced).
__device__ __forceinline__ void ldq(ulonglong2 v[4], const float* base) {
#pragma unroll
    for (int c = 0; c < 4; ++c)
        v[c] = *reinterpret_cast<const ulonglong2*>(base + (size_t)c * SN);
}

__global__ __launch_bounds__(BLOCK, 2) void fused_proj_ln_r14(
    const float* __restrict__ x,
    const float* __restrict__ Wp,
    const float* __restrict__ bp,
    const float* __restrict__ gp,
    const float* __restrict__ hp,
    float* __restrict__ out)
{
    __shared__ u64 sW2[CN * CN];          // (w,w) duplicated pairs
    __shared__ u64 sb2[CN], sg2[CN], sh2[CN];

    const int t = threadIdx.x;
    if (t < CN * CN) { const float w = Wp[t]; sW2[t] = pack2(w, w); }
    if (t < CN) {
        sb2[t] = pack2(bp[t], bp[t]);
        sg2[t] = pack2(gp[t], gp[t]);
        sh2[t] = pack2(hp[t], hp[t]);
    }
    __syncthreads();

    const unsigned g0     = blockIdx.x * (unsigned)BLOCK + (unsigned)t;
    const unsigned stride = GRIDN * (unsigned)BLOCK;        // 75,776

    // Current-tile coordinates, carried across iterations.
    unsigned b  = g0 / GPB;
    unsigned s4 = (g0 - b * GPB) * 4u;
    const float* xb = x + (size_t)b * (CN * SN) + s4;

    ulonglong2 v0[4], v1[4];
    ldq(v0, xb);                          // prologue: Q0 of first tile

    for (unsigned u = g0; u < TUNITS; u += stride) {
        // y accumulators: lo pair = s4+0,1 ; hi pair = s4+2,3.
        u64 ylo[CN], yhi[CN];
#pragma unroll
        for (int j = 0; j < CN; ++j) { ylo[j] = sb2[j]; yhi[j] = sb2[j]; }

        // -------- Q1 load, then Q0 FMA --------
        ldq(v1, xb + 4 * SN);
#pragma unroll
        for (int j = 0; j < CN; ++j) {
            u64 alo = ylo[j], ahi = yhi[j];
#pragma unroll
            for (int c = 0; c < 4; ++c) {
                const u64 w = sW2[j * CN + c];
                alo = fma2(w, v0[c].x, alo);
                ahi = fma2(w, v0[c].y, ahi);
            }
            ylo[j] = alo; yhi[j] = ahi;
        }

        // -------- Q2 load, then Q1 FMA --------
        ldq(v0, xb + 8 * SN);
#pragma unroll
        for (int j = 0; j < CN; ++j) {
            u64 alo = ylo[j], ahi = yhi[j];
#pragma unroll
            for (int c = 0; c < 4; ++c) {
                const u64 w = sW2[j * CN + 4 + c];
                alo = fma2(w, v1[c].x, alo);
                ahi = fma2(w, v1[c].y, ahi);
            }
            ylo[j] = alo; yhi[j] = ahi;
        }

        // -------- Q3 load, then Q2 FMA --------
        ldq(v1, xb + 12 * SN);
#pragma unroll
        for (int j = 0; j < CN; ++j) {
            u64 alo = ylo[j], ahi = yhi[j];
#pragma unroll
            for (int c = 0; c < 4; ++c) {
                const u64 w = sW2[j * CN + 8 + c];
                alo = fma2(w, v0[c].x, alo);
                ahi = fma2(w, v0[c].y, ahi);
            }
            ylo[j] = alo; yhi[j] = ahi;
        }

        // -------- next-tile Q0 prefetch (in flight through Q3 FMA + LN + stores) --------
        {
            const unsigned un = u + stride;
            unsigned bn = 0, s4n = 0;
            if (un < TUNITS) { bn = un / GPB; s4n = (un - bn * GPB) * 4u; }
            const float* xbn = x + (size_t)bn * (CN * SN) + s4n;  // clamped to tile 0 when done
            ldq(v0, xbn);
            b = bn; s4 = s4n;
            // current tile's output pointer before xb is overwritten
            float* ob = out + (size_t)(xb - x);
            xb = xbn;

            // -------- Q3 FMA --------
#pragma unroll
            for (int j = 0; j < CN; ++j) {
                u64 alo = ylo[j], ahi = yhi[j];
#pragma unroll
                for (int c = 0; c < 4; ++c) {
                    const u64 w = sW2[j * CN + 12 + c];
                    alo = fma2(w, v1[c].x, alo);
                    ahi = fma2(w, v1[c].y, ahi);
                }
                ylo[j] = alo; yhi[j] = ahi;
            }

            // -------- LayerNorm --------
            u64 slo = ylo[0], shi = yhi[0];
#pragma unroll
            for (int j = 1; j < CN; ++j) { slo = add2(slo, ylo[j]); shi = add2(shi, yhi[j]); }
            const u64 ninv2  = pack2(-1.0f / (float)CN, -1.0f / (float)CN);
            const u64 negmul = mul2(slo, ninv2);
            const u64 negmuh = mul2(shi, ninv2);

            u64 vlo = 0ull, vhi = 0ull;
#pragma unroll
            for (int j = 0; j < CN; ++j) {
                const u64 dlo = add2(ylo[j], negmul);
                const u64 dhi = add2(yhi[j], negmuh);
                vlo = fma2(dlo, dlo, vlo);
                vhi = fma2(dhi, dhi, vhi);
            }
            float va, vb2, vc2, vd;
            unpack2(vlo, va, vb2);
            unpack2(vhi, vc2, vd);
            const float inv = 1.0f / (float)CN;
            const u64 rslo = pack2(rsqrtf(va  * inv + LN_EPS), rsqrtf(vb2 * inv + LN_EPS));
            const u64 rshi = pack2(rsqrtf(vc2 * inv + LN_EPS), rsqrtf(vd  * inv + LN_EPS));

            // -------- stores (STG.cs, write-once stream) --------
#pragma unroll
            for (int j = 0; j < CN; ++j) {
                const u64 g2 = sg2[j];
                const u64 h2 = sh2[j];
                const u64 dlo = add2(ylo[j], negmul);
                const u64 dhi = add2(yhi[j], negmuh);
                stcs128(ob + (size_t)j * SN,
                        fma2(mul2(dlo, rslo), g2, h2),
                        fma2(mul2(dhi, rshi), g2, h2));
            }
        }
    }
}

extern "C" void kernel_launch(void* const* d_in, const int* in_sizes, int n_in,
                              void* d_out, int out_size)
{
    // metadata order: x, Wq, bq, gq, hq, Wk, bk, gk, hk, Wp, bp, gp, hp
    const float* x  = (const float*)d_in[0];
    const float* Wp = (const float*)d_in[9];
    const float* bp = (const float*)d_in[10];
    const float* gp = (const float*)d_in[11];
    const float* hp = (const float*)d_in[12];
    float* out = (float*)d_out;

    fused_proj_ln_r14<<<GRIDN, BLOCK>>>(x, Wp, bp, gp, hp, out);
}

// round 16
// speedup vs baseline: 2.3365x; 1.0158x over previous
#include <cuda_runtime.h>
#include <cuda_bf16.h>
#include <cstdint>

// x[B=2048, C=16, S=2000] fp32.
// Attention branch is identity (softmax rows sum to 1), so:
//   out[b,j,s] = LN_j( sum_c Wp[j,c]*x[b,c,s] + bp[j] ) * gp[j] + hp[j]
//
// R16 = R14 (persistent 296x256, packed FFMA2, 2-buffer SW pipeline, STG.cs)
// with two micro-fixes:
//  (1) schedule rotated one notch so next-tile Q0 AND Q1 are in flight during
//      the LN+store epilogue (R14 entered it with only Q0 outstanding);
//  (2) x loads use ld.global.cs (read-once stream; stop thrashing L1/L2
//      against the write stream).

#define CN      16
#define SN      2000
#define BN      2048
#define LN_EPS  1e-5f
#define GRIDN   296
#define BLOCK   256
#define GPB     500                       // 4-s units per b
#define TUNITS  ((unsigned)BN * GPB)      // 1,024,000 thread-units

typedef unsigned long long u64;

__device__ __forceinline__ u64 fma2(u64 a, u64 b, u64 c) {
    u64 d; asm("fma.rn.f32x2 %0, %1, %2, %3;" : "=l"(d) : "l"(a), "l"(b), "l"(c)); return d;
}
__device__ __forceinline__ u64 add2(u64 a, u64 b) {
    u64 d; asm("add.rn.f32x2 %0, %1, %2;" : "=l"(d) : "l"(a), "l"(b)); return d;
}
__device__ __forceinline__ u64 mul2(u64 a, u64 b) {
    u64 d; asm("mul.rn.f32x2 %0, %1, %2;" : "=l"(d) : "l"(a), "l"(b)); return d;
}
__device__ __forceinline__ u64 pack2(float lo, float hi) {
    u64 d; asm("mov.b64 %0, {%1, %2};" : "=l"(d) : "f"(lo), "f"(hi)); return d;
}
__device__ __forceinline__ void unpack2(u64 a, float& lo, float& hi) {
    asm("mov.b64 {%0, %1}, %2;" : "=f"(lo), "=f"(hi) : "l"(a));
}
__device__ __forceinline__ void stcs128(float* p, u64 lo, u64 hi) {
    asm volatile("st.global.cs.v2.b64 [%0], {%1, %2};" :: "l"(p), "l"(lo), "l"(hi) : "memory");
}

// Load a 4-channel quarter: 4x LDG.128 with evict-first (.cs) policy.
__device__ __forceinline__ void ldq(ulonglong2 v[4], const float* base) {
#pragma unroll
    for (int c = 0; c < 4; ++c)
        asm volatile("ld.global.cs.v2.u64 {%0, %1}, [%2];"
                     : "=l"(v[c].x), "=l"(v[c].y)
                     : "l"(base + (size_t)c * SN));
}

__global__ __launch_bounds__(BLOCK, 2) void fused_proj_ln_r16(
    const float* __restrict__ x,
    const float* __restrict__ Wp,
    const float* __restrict__ bp,
    const float* __restrict__ gp,
    const float* __restrict__ hp,
    float* __restrict__ out)
{
    __shared__ u64 sW2[CN * CN];          // (w,w) duplicated pairs
    __shared__ u64 sb2[CN], sg2[CN], sh2[CN];

    const int t = threadIdx.x;
    if (t < CN * CN) { const float w = Wp[t]; sW2[t] = pack2(w, w); }
    if (t < CN) {
        sb2[t] = pack2(bp[t], bp[t]);
        sg2[t] = pack2(gp[t], gp[t]);
        sh2[t] = pack2(hp[t], hp[t]);
    }
    __syncthreads();

    const unsigned g0     = blockIdx.x * (unsigned)BLOCK + (unsigned)t;
    const unsigned stride = GRIDN * (unsigned)BLOCK;        // 75,776

    unsigned b  = g0 / GPB;
    unsigned s4 = (g0 - b * GPB) * 4u;
    const float* xb = x + (size_t)b * (CN * SN) + s4;

    ulonglong2 v0[4], v1[4];
    // Prologue: first tile's Q0 and Q1 both in flight before the loop.
    ldq(v0, xb);
    ldq(v1, xb + 4 * SN);

    for (unsigned u = g0; u < TUNITS; u += stride) {
        float* ob = out + (size_t)(xb - x);

        u64 ylo[CN], yhi[CN];

        // -------- fma Q0 (v0, W cols 0..3); Q1 already in flight --------
#pragma unroll
        for (int j = 0; j < CN; ++j) {
            u64 alo = sb2[j], ahi = sb2[j];
#pragma unroll
            for (int c = 0; c < 4; ++c) {
                const u64 w = sW2[j * CN + c];
                alo = fma2(w, v0[c].x, alo);
                ahi = fma2(w, v0[c].y, ahi);
            }
            ylo[j] = alo; yhi[j] = ahi;
        }
        ldq(v0, xb + 8 * SN);             // Q2 -> v0

        // -------- fma Q1 (v1, cols 4..7) --------
#pragma unroll
        for (int j = 0; j < CN; ++j) {
            u64 alo = ylo[j], ahi = yhi[j];
#pragma unroll
            for (int c = 0; c < 4; ++c) {
                const u64 w = sW2[j * CN + 4 + c];
                alo = fma2(w, v1[c].x, alo);
                ahi = fma2(w, v1[c].y, ahi);
            }
            ylo[j] = alo; yhi[j] = ahi;
        }
        ldq(v1, xb + 12 * SN);            // Q3 -> v1

        // -------- fma Q2 (v0, cols 8..11) --------
#pragma unroll
        for (int j = 0; j < CN; ++j) {
            u64 alo = ylo[j], ahi = yhi[j];
#pragma unroll
            for (int c = 0; c < 4; ++c) {
                const u64 w = sW2[j * CN + 8 + c];
                alo = fma2(w, v0[c].x, alo);
                ahi = fma2(w, v0[c].y, ahi);
            }
            ylo[j] = alo; yhi[j] = ahi;
        }

        // next-tile base (clamped to tile 0 on the last round; loads stay
        // in-bounds, results unused)
        const unsigned un = u + stride;
        unsigned bn = 0, s4n = 0;
        if (un < TUNITS) { bn = un / GPB; s4n = (un - bn * GPB) * 4u; }
        const float* xbn = x + (size_t)bn * (CN * SN) + s4n;

        ldq(v0, xbn);                     // next Q0 -> v0

        // -------- fma Q3 (v1, cols 12..15) --------
#pragma unroll
        for (int j = 0; j < CN; ++j) {
            u64 alo = ylo[j], ahi = yhi[j];
#pragma unroll
            for (int c = 0; c < 4; ++c) {
                const u64 w = sW2[j * CN + 12 + c];
                alo = fma2(w, v1[c].x, alo);
                ahi = fma2(w, v1[c].y, ahi);
            }
            ylo[j] = alo; yhi[j] = ahi;
        }
        ldq(v1, xbn + 4 * SN);            // next Q1 -> v1   (8 loads in flight)
        xb = xbn;

        // -------- LayerNorm (epilogue fully overlapped with nQ0+nQ1) --------
        u64 slo = ylo[0], shi = yhi[0];
#pragma unroll
        for (int j = 1; j < CN; ++j) { slo = add2(slo, ylo[j]); shi = add2(shi, yhi[j]); }
        const u64 ninv2  = pack2(-1.0f / (float)CN, -1.0f / (float)CN);
        const u64 negmul = mul2(slo, ninv2);
        const u64 negmuh = mul2(shi, ninv2);

        u64 vlo = 0ull, vhi = 0ull;
#pragma unroll
        for (int j = 0; j < CN; ++j) {
            const u64 dlo = add2(ylo[j], negmul);
            const u64 dhi = add2(yhi[j], negmuh);
            vlo = fma2(dlo, dlo, vlo);
            vhi = fma2(dhi, dhi, vhi);
        }
        float va, vb2, vc2, vd;
        unpack2(vlo, va, vb2);
        unpack2(vhi, vc2, vd);
        const float inv = 1.0f / (float)CN;
        const u64 rslo = pack2(rsqrtf(va  * inv + LN_EPS), rsqrtf(vb2 * inv + LN_EPS));
        const u64 rshi = pack2(rsqrtf(vc2 * inv + LN_EPS), rsqrtf(vd  * inv + LN_EPS));

#pragma unroll
        for (int j = 0; j < CN; ++j) {
            const u64 g2 = sg2[j];
            const u64 h2 = sh2[j];
            const u64 dlo = add2(ylo[j], negmul);
            const u64 dhi = add2(yhi[j], negmuh);
            stcs128(ob + (size_t)j * SN,
                    fma2(mul2(dlo, rslo), g2, h2),
                    fma2(mul2(dhi, rshi), g2, h2));
        }
    }
}

extern "C" void kernel_launch(void* const* d_in, const int* in_sizes, int n_in,
                              void* d_out, int out_size)
{
    // metadata order: x, Wq, bq, gq, hq, Wk, bk, gk, hk, Wp, bp, gp, hp
    const float* x  = (const float*)d_in[0];
    const float* Wp = (const float*)d_in[9];
    const float* bp = (const float*)d_in[10];
    const float* gp = (const float*)d_in[11];
    const float* hp = (const float*)d_in[12];
    float* out = (float*)d_out;

    fused_proj_ln_r16<<<GRIDN, BLOCK>>>(x, Wp, bp, gp, hp, out);
}

// round 17
// speedup vs baseline: 2.3618x; 1.0108x over previous
#include <cuda_runtime.h>
#include <cuda_bf16.h>
#include <cstdint>

// x[B=2048, C=16, S=2000] fp32.
// Attention branch is identity (softmax rows sum to 1), so:
//   out[b,j,s] = LN_j( sum_c Wp[j,c]*x[b,c,s] + bp[j] ) * gp[j] + hp[j]
//
// R17 = R16 (persistent 296x256, packed FFMA2, rotated 2-buffer SW pipeline,
// ld.global.cs / st.global.cs) with a shortened epilogue:
//  (1) variance via E[y^2] - mu^2 (fused sumsq; halves the var pass),
//  (2) store math pre-fused: out = y*(rs*g) + (h - mu*rs*g).

#define CN      16
#define SN      2000
#define BN      2048
#define LN_EPS  1e-5f
#define GRIDN   296
#define BLOCK   256
#define GPB     500                       // 4-s units per b
#define TUNITS  ((unsigned)BN * GPB)      // 1,024,000 thread-units

typedef unsigned long long u64;

__device__ __forceinline__ u64 fma2(u64 a, u64 b, u64 c) {
    u64 d; asm("fma.rn.f32x2 %0, %1, %2, %3;" : "=l"(d) : "l"(a), "l"(b), "l"(c)); return d;
}
__device__ __forceinline__ u64 add2(u64 a, u64 b) {
    u64 d; asm("add.rn.f32x2 %0, %1, %2;" : "=l"(d) : "l"(a), "l"(b)); return d;
}
__device__ __forceinline__ u64 mul2(u64 a, u64 b) {
    u64 d; asm("mul.rn.f32x2 %0, %1, %2;" : "=l"(d) : "l"(a), "l"(b)); return d;
}
__device__ __forceinline__ u64 pack2(float lo, float hi) {
    u64 d; asm("mov.b64 %0, {%1, %2};" : "=l"(d) : "f"(lo), "f"(hi)); return d;
}
__device__ __forceinline__ void unpack2(u64 a, float& lo, float& hi) {
    asm("mov.b64 {%0, %1}, %2;" : "=f"(lo), "=f"(hi) : "l"(a));
}
__device__ __forceinline__ void stcs128(float* p, u64 lo, u64 hi) {
    asm volatile("st.global.cs.v2.b64 [%0], {%1, %2};" :: "l"(p), "l"(lo), "l"(hi) : "memory");
}

// Load a 4-channel quarter: 4x LDG.128 with evict-first (.cs) policy.
__device__ __forceinline__ void ldq(ulonglong2 v[4], const float* base) {
#pragma unroll
    for (int c = 0; c < 4; ++c)
        asm volatile("ld.global.cs.v2.u64 {%0, %1}, [%2];"
                     : "=l"(v[c].x), "=l"(v[c].y)
                     : "l"(base + (size_t)c * SN));
}

__global__ __launch_bounds__(BLOCK, 2) void fused_proj_ln_r17(
    const float* __restrict__ x,
    const float* __restrict__ Wp,
    const float* __restrict__ bp,
    const float* __restrict__ gp,
    const float* __restrict__ hp,
    float* __restrict__ out)
{
    __shared__ u64 sW2[CN * CN];          // (w,w) duplicated pairs
    __shared__ u64 sb2[CN], sg2[CN], sh2[CN];

    const int t = threadIdx.x;
    if (t < CN * CN) { const float w = Wp[t]; sW2[t] = pack2(w, w); }
    if (t < CN) {
        sb2[t] = pack2(bp[t], bp[t]);
        sg2[t] = pack2(gp[t], gp[t]);
        sh2[t] = pack2(hp[t], hp[t]);
    }
    __syncthreads();

    const unsigned g0     = blockIdx.x * (unsigned)BLOCK + (unsigned)t;
    const unsigned stride = GRIDN * (unsigned)BLOCK;        // 75,776

    unsigned b  = g0 / GPB;
    unsigned s4 = (g0 - b * GPB) * 4u;
    const float* xb = x + (size_t)b * (CN * SN) + s4;

    ulonglong2 v0[4], v1[4];
    // Prologue: first tile's Q0 and Q1 both in flight before the loop.
    ldq(v0, xb);
    ldq(v1, xb + 4 * SN);

    for (unsigned u = g0; u < TUNITS; u += stride) {
        float* ob = out + (size_t)(xb - x);

        u64 ylo[CN], yhi[CN];

        // -------- fma Q0 (v0, W cols 0..3); Q1 already in flight --------
#pragma unroll
        for (int j = 0; j < CN; ++j) {
            u64 alo = sb2[j], ahi = sb2[j];
#pragma unroll
            for (int c = 0; c < 4; ++c) {
                const u64 w = sW2[j * CN + c];
                alo = fma2(w, v0[c].x, alo);
                ahi = fma2(w, v0[c].y, ahi);
            }
            ylo[j] = alo; yhi[j] = ahi;
        }
        ldq(v0, xb + 8 * SN);             // Q2 -> v0

        // -------- fma Q1 (v1, cols 4..7) --------
#pragma unroll
        for (int j = 0; j < CN; ++j) {
            u64 alo = ylo[j], ahi = yhi[j];
#pragma unroll
            for (int c = 0; c < 4; ++c) {
                const u64 w = sW2[j * CN + 4 + c];
                alo = fma2(w, v1[c].x, alo);
                ahi = fma2(w, v1[c].y, ahi);
            }
            ylo[j] = alo; yhi[j] = ahi;
        }
        ldq(v1, xb + 12 * SN);            // Q3 -> v1

        // -------- fma Q2 (v0, cols 8..11) --------
#pragma unroll
        for (int j = 0; j < CN; ++j) {
            u64 alo = ylo[j], ahi = yhi[j];
#pragma unroll
            for (int c = 0; c < 4; ++c) {
                const u64 w = sW2[j * CN + 8 + c];
                alo = fma2(w, v0[c].x, alo);
                ahi = fma2(w, v0[c].y, ahi);
            }
            ylo[j] = alo; yhi[j] = ahi;
        }

        // next-tile base (clamped to tile 0 on the last round; loads stay
        // in-bounds, results unused)
        const unsigned un = u + stride;
        unsigned bn = 0, s4n = 0;
        if (un < TUNITS) { bn = un / GPB; s4n = (un - bn * GPB) * 4u; }
        const float* xbn = x + (size_t)bn * (CN * SN) + s4n;

        ldq(v0, xbn);                     // next Q0 -> v0

        // -------- fma Q3 (v1, cols 12..15) --------
#pragma unroll
        for (int j = 0; j < CN; ++j) {
            u64 alo = ylo[j], ahi = yhi[j];
#pragma unroll
            for (int c = 0; c < 4; ++c) {
                const u64 w = sW2[j * CN + 12 + c];
                alo = fma2(w, v1[c].x, alo);
                ahi = fma2(w, v1[c].y, ahi);
            }
            ylo[j] = alo; yhi[j] = ahi;
        }
        ldq(v1, xbn + 4 * SN);            // next Q1 -> v1   (8 loads in flight)
        xb = xbn;

        // -------- LayerNorm epilogue (shortened; overlapped with nQ0+nQ1) ----
        // sum and sum of squares in one sweep: var = E[y^2] - mu^2
        u64 slo = ylo[0],               shi = yhi[0];
        u64 qlo = mul2(ylo[0], ylo[0]), qhi = mul2(yhi[0], yhi[0]);
#pragma unroll
        for (int j = 1; j < CN; ++j) {
            slo = add2(slo, ylo[j]);
            shi = add2(shi, yhi[j]);
            qlo = fma2(ylo[j], ylo[j], qlo);
            qhi = fma2(yhi[j], yhi[j], qhi);
        }
        const u64 inv2 = pack2(1.0f / (float)CN, 1.0f / (float)CN);
        const u64 mulo = mul2(slo, inv2);          // mu
        const u64 muhi = mul2(shi, inv2);
        const u64 eylo = mul2(qlo, inv2);          // E[y^2]
        const u64 eyhi = mul2(qhi, inv2);

        float m0, m1, m2, m3, e0, e1, e2, e3;
        unpack2(mulo, m0, m1);
        unpack2(muhi, m2, m3);
        unpack2(eylo, e0, e1);
        unpack2(eyhi, e2, e3);
        const u64 rslo = pack2(rsqrtf(fmaxf(e0 - m0 * m0, 0.f) + LN_EPS),
                               rsqrtf(fmaxf(e1 - m1 * m1, 0.f) + LN_EPS));
        const u64 rshi = pack2(rsqrtf(fmaxf(e2 - m2 * m2, 0.f) + LN_EPS),
                               rsqrtf(fmaxf(e3 - m3 * m3, 0.f) + LN_EPS));
        const u64 nmulo = pack2(-m0, -m1);
        const u64 nmuhi = pack2(-m2, -m3);

        // out = y*(rs*g) + (h - mu*rs*g): per j, a=rs*g (2 mul), b=fma(-mu,a,h),
        // o=fma(y,a,b) -> 4 packed ops per j per half-pair group.
#pragma unroll
        for (int j = 0; j < CN; ++j) {
            const u64 alo = mul2(rslo, sg2[j]);
            const u64 ahi = mul2(rshi, sg2[j]);
            const u64 blo = fma2(nmulo, alo, sh2[j]);
            const u64 bhi = fma2(nmuhi, ahi, sh2[j]);
            stcs128(ob + (size_t)j * SN,
                    fma2(ylo[j], alo, blo),
                    fma2(yhi[j], ahi, bhi));
        }
    }
}

extern "C" void kernel_launch(void* const* d_in, const int* in_sizes, int n_in,
                              void* d_out, int out_size)
{
    // metadata order: x, Wq, bq, gq, hq, Wk, bk, gk, hk, Wp, bp, gp, hp
    const float* x  = (const float*)d_in[0];
    const float* Wp = (const float*)d_in[9];
    const float* bp = (const float*)d_in[10];
    const float* gp = (const float*)d_in[11];
    const float* hp = (const float*)d_in[12];
    float* out = (float*)d_out;

    fused_proj_ln_r17<<<GRIDN, BLOCK>>>(x, Wp, bp, gp, hp, out);
}